// round 1
// baseline (speedup 1.0000x reference)
#include <cuda_runtime.h>
#include <cstdint>

#define E_NUM   500000
#define N_NUM   100000
#define H_DIM   256
#define PAIRS   (E_NUM / 2)          // 250000 (E is even)
#define BN_EPS  1e-5f
#define NBLK1   ((PAIRS + 255) / 256)  // 977

typedef unsigned long long u64;

// -------- device scratch (no allocation allowed) --------
__device__ float g_sum[H_DIM];
__device__ float g_sumsq[H_DIM];
__device__ u64   g_nc2[PAIRS * 8];      // packed nc pairs, 16 MB
__device__ float g_P1[H_DIM * 8];       // Wo@Wp
__device__ float g_P2[H_DIM * 8];       // Wv@P1
__device__ float g_a[H_DIM];            // bn scale
__device__ u64   g_dhdup[8];            // 0.5*d duplicated
__device__ u64   g_w1dup[H_DIM * 8];    // W1^T duplicated (j,d)
__device__ u64   g_b1dup[H_DIM];
__device__ u64   g_mdup[H_DIM * 8];     // 0.5*a[j]*C[j,k] duplicated

// -------- f32x2 helpers --------
__device__ __forceinline__ u64 pack2(float lo, float hi) {
    u64 r;
    asm("mov.b64 %0, {%1, %2};" : "=l"(r)
        : "r"(__float_as_uint(lo)), "r"(__float_as_uint(hi)));
    return r;
}
__device__ __forceinline__ void unpack2(u64 v, float &lo, float &hi) {
    unsigned int a, b;
    asm("mov.b64 {%0, %1}, %2;" : "=r"(a), "=r"(b) : "l"(v));
    lo = __uint_as_float(a); hi = __uint_as_float(b);
}
__device__ __forceinline__ u64 fma2(u64 a, u64 b, u64 c) {
    u64 d;
    asm("fma.rn.f32x2 %0, %1, %2, %3;" : "=l"(d) : "l"(a), "l"(b), "l"(c));
    return d;
}
__device__ __forceinline__ u64 add2(u64 a, u64 b) {
    u64 d;
    asm("add.rn.f32x2 %0, %1, %2;" : "=l"(d) : "l"(a), "l"(b));
    return d;
}
__device__ __forceinline__ u64 relu2(u64 h) {
    float lo, hi; unpack2(h, lo, hi);
    return pack2(fmaxf(lo, 0.f), fmaxf(hi, 0.f));
}

// -------- kA: P1 = Wo@Wp, build w1dup/b1dup, zero stats --------
__global__ void kA(const float* __restrict__ Wo, const float* __restrict__ Wp,
                   const float* __restrict__ W1, const float* __restrict__ b1) {
    __shared__ float wp_s[H_DIM * 8];
    int t = threadIdx.x;
    int tid = blockIdx.x * 256 + t;
    for (int i = t; i < H_DIM * 8; i += 256) wp_s[i] = Wp[i];
    __syncthreads();
    int j = tid >> 3, k = tid & 7;
    const float* row = Wo + j * H_DIM;
    float acc = 0.f;
    #pragma unroll 8
    for (int q = 0; q < H_DIM; q++) acc = fmaf(row[q], wp_s[q * 8 + k], acc);
    g_P1[j * 8 + k] = acc;
    float wv = W1[k * H_DIM + j];          // W1 is [8,256] row-major; d=k
    g_w1dup[j * 8 + k] = pack2(wv, wv);
    if (tid < H_DIM) {
        float b = b1[tid];
        g_b1dup[tid] = pack2(b, b);
        g_sum[tid] = 0.f;
        g_sumsq[tid] = 0.f;
    }
}

// -------- kB: P2 = Wv@P1 --------
__global__ void kB(const float* __restrict__ Wv) {
    __shared__ float p1_s[H_DIM * 8];
    int t = threadIdx.x;
    int tid = blockIdx.x * 256 + t;
    for (int i = t; i < H_DIM * 8; i += 256) p1_s[i] = g_P1[i];
    __syncthreads();
    int j = tid >> 3, k = tid & 7;
    const float* row = Wv + j * H_DIM;
    float acc = 0.f;
    #pragma unroll 8
    for (int q = 0; q < H_DIM; q++) acc = fmaf(row[q], p1_s[q * 8 + k], acc);
    g_P2[j * 8 + k] = acc;
}

// -------- k1: gather nc, cache it packed, per-column relu stats --------
__global__ void __launch_bounds__(256) k1(const int* __restrict__ eidx,
                                          const float* __restrict__ nf) {
    __shared__ u64 ncs[256 * 8];
    int t = threadIdx.x;
    int base = blockIdx.x * 256;
    int cnt = min(256, PAIRS - base);
    const float4* nf4 = (const float4*)nf;

    if (t < cnt) {
        int p  = base + t;
        int e0 = 2 * p;
        int sA = eidx[e0],        sB = eidx[e0 + 1];
        int dA = eidx[E_NUM + e0], dB = eidx[E_NUM + e0 + 1];
        float4 sa0 = nf4[2 * sA], sa1 = nf4[2 * sA + 1];
        float4 da0 = nf4[2 * dA], da1 = nf4[2 * dA + 1];
        float4 sb0 = nf4[2 * sB], sb1 = nf4[2 * sB + 1];
        float4 db0 = nf4[2 * dB], db1 = nf4[2 * dB + 1];

        u64 ncp[8];
        ncp[0] = pack2(0.5f * (sa0.x + da0.x), 0.5f * (sb0.x + db0.x));
        ncp[1] = pack2(0.5f * (sa0.y + da0.y), 0.5f * (sb0.y + db0.y));
        ncp[2] = pack2(0.5f * (sa0.z + da0.z), 0.5f * (sb0.z + db0.z));
        ncp[3] = pack2(0.5f * (sa0.w + da0.w), 0.5f * (sb0.w + db0.w));
        ncp[4] = pack2(0.5f * (sa1.x + da1.x), 0.5f * (sb1.x + db1.x));
        ncp[5] = pack2(0.5f * (sa1.y + da1.y), 0.5f * (sb1.y + db1.y));
        ncp[6] = pack2(0.5f * (sa1.z + da1.z), 0.5f * (sb1.z + db1.z));
        ncp[7] = pack2(0.5f * (sa1.w + da1.w), 0.5f * (sb1.w + db1.w));

        #pragma unroll
        for (int d = 0; d < 8; d++) ncs[t * 8 + d] = ncp[d];
        ulonglong2* dst = (ulonglong2*)&g_nc2[(size_t)p * 8];
        dst[0] = make_ulonglong2(ncp[0], ncp[1]);
        dst[1] = make_ulonglong2(ncp[2], ncp[3]);
        dst[2] = make_ulonglong2(ncp[4], ncp[5]);
        dst[3] = make_ulonglong2(ncp[6], ncp[7]);
    }
    __syncthreads();

    int j = t;  // this thread owns hidden column j
    const ulonglong2* wd = (const ulonglong2*)&g_w1dup[j * 8];
    ulonglong2 w01 = wd[0], w23 = wd[1], w45 = wd[2], w67 = wd[3];
    u64 bdup = g_b1dup[j];
    u64 sum2 = 0ull, sq2 = 0ull;

    #pragma unroll 2
    for (int e2 = 0; e2 < cnt; e2++) {
        const ulonglong2* c = (const ulonglong2*)&ncs[e2 * 8];
        ulonglong2 c01 = c[0], c23 = c[1], c45 = c[2], c67 = c[3];
        u64 h = bdup;
        h = fma2(c01.x, w01.x, h); h = fma2(c01.y, w01.y, h);
        h = fma2(c23.x, w23.x, h); h = fma2(c23.y, w23.y, h);
        h = fma2(c45.x, w45.x, h); h = fma2(c45.y, w45.y, h);
        h = fma2(c67.x, w67.x, h); h = fma2(c67.y, w67.y, h);
        h = relu2(h);
        sum2 = add2(sum2, h);
        sq2  = fma2(h, h, sq2);
    }
    float slo, shi, qlo, qhi;
    unpack2(sum2, slo, shi);
    unpack2(sq2, qlo, qhi);
    atomicAdd(&g_sum[j],   slo + shi);
    atomicAdd(&g_sumsq[j], qlo + qhi);
}

// -------- kV: finalize stats, bias chain d = (((c@W2+b2)@Wv+bv)@Wo+bo)@Wp+bp --------
__global__ void kV(const float* __restrict__ gamma, const float* __restrict__ beta,
                   const float* __restrict__ W2, const float* __restrict__ b2,
                   const float* __restrict__ Wv, const float* __restrict__ bv,
                   const float* __restrict__ Wo, const float* __restrict__ bo,
                   const float* __restrict__ Wp, const float* __restrict__ bp) {
    __shared__ float c_s[H_DIM], x_s[H_DIM], y_s[H_DIM];
    int t = threadIdx.x;
    const float invE = 1.f / (float)E_NUM;
    float mu  = g_sum[t] * invE;
    float var = g_sumsq[t] * invE - mu * mu;
    float aj  = gamma[t] * rsqrtf(var + BN_EPS);
    g_a[t] = aj;
    c_s[t] = beta[t] - mu * aj;
    __syncthreads();
    float acc = b2[t];
    #pragma unroll 8
    for (int q = 0; q < H_DIM; q++) acc = fmaf(c_s[q], W2[q * H_DIM + t], acc);
    x_s[t] = acc;
    __syncthreads();
    acc = bv[t];
    #pragma unroll 8
    for (int q = 0; q < H_DIM; q++) acc = fmaf(x_s[q], Wv[q * H_DIM + t], acc);
    y_s[t] = acc;
    __syncthreads();
    acc = bo[t];
    #pragma unroll 8
    for (int q = 0; q < H_DIM; q++) acc = fmaf(y_s[q], Wo[q * H_DIM + t], acc);
    c_s[t] = acc;   // reuse as w3
    __syncthreads();
    if (t < 8) {
        float d = bp[t];
        for (int q = 0; q < H_DIM; q++) d = fmaf(c_s[q], Wp[q * 8 + t], d);
        d *= 0.5f;
        g_dhdup[t] = pack2(d, d);
    }
}

// -------- kC: C = W2@P2, mdup = 0.5*a[j]*C duplicated --------
__global__ void kC(const float* __restrict__ W2) {
    __shared__ float p2_s[H_DIM * 8];
    int t = threadIdx.x;
    int tid = blockIdx.x * 256 + t;
    for (int i = t; i < H_DIM * 8; i += 256) p2_s[i] = g_P2[i];
    __syncthreads();
    int j = tid >> 3, k = tid & 7;
    const float* row = W2 + j * H_DIM;
    float acc = 0.f;
    #pragma unroll 8
    for (int q = 0; q < H_DIM; q++) acc = fmaf(row[q], p2_s[q * 8 + k], acc);
    float m = 0.5f * g_a[j] * acc;
    g_mdup[j * 8 + k] = pack2(m, m);
}

// -------- k3: main pass, two edges per thread via f32x2 --------
__global__ void __launch_bounds__(256) k3(const float* __restrict__ ea,
                                          float* __restrict__ out) {
    __shared__ u64 w1s[H_DIM * 8];
    __shared__ u64 ms[H_DIM * 8];
    __shared__ u64 b1s[H_DIM];
    int t = threadIdx.x;
    {
        ulonglong2* wd = (ulonglong2*)w1s;
        ulonglong2* md = (ulonglong2*)ms;
        const ulonglong2* wsrc = (const ulonglong2*)g_w1dup;
        const ulonglong2* msrc = (const ulonglong2*)g_mdup;
        #pragma unroll
        for (int i = t; i < H_DIM * 4; i += 256) { wd[i] = wsrc[i]; md[i] = msrc[i]; }
        b1s[t] = g_b1dup[t];
    }
    __syncthreads();

    int p = blockIdx.x * 256 + t;
    if (p >= PAIRS) return;

    const ulonglong2* ncg = (const ulonglong2*)&g_nc2[(size_t)p * 8];
    ulonglong2 n01 = ncg[0], n23 = ncg[1], n45 = ncg[2], n67 = ncg[3];

    u64 acc0 = g_dhdup[0], acc1 = g_dhdup[1], acc2 = g_dhdup[2], acc3 = g_dhdup[3];
    u64 acc4 = g_dhdup[4], acc5 = g_dhdup[5], acc6 = g_dhdup[6], acc7 = g_dhdup[7];

    #pragma unroll 4
    for (int j = 0; j < H_DIM; j++) {
        const ulonglong2* w = (const ulonglong2*)&w1s[j * 8];
        ulonglong2 w01 = w[0], w23 = w[1], w45 = w[2], w67 = w[3];
        u64 h = b1s[j];
        h = fma2(n01.x, w01.x, h); h = fma2(n01.y, w01.y, h);
        h = fma2(n23.x, w23.x, h); h = fma2(n23.y, w23.y, h);
        h = fma2(n45.x, w45.x, h); h = fma2(n45.y, w45.y, h);
        h = fma2(n67.x, w67.x, h); h = fma2(n67.y, w67.y, h);
        h = relu2(h);
        const ulonglong2* m = (const ulonglong2*)&ms[j * 8];
        ulonglong2 m01 = m[0], m23 = m[1], m45 = m[2], m67 = m[3];
        acc0 = fma2(h, m01.x, acc0); acc1 = fma2(h, m01.y, acc1);
        acc2 = fma2(h, m23.x, acc2); acc3 = fma2(h, m23.y, acc3);
        acc4 = fma2(h, m45.x, acc4); acc5 = fma2(h, m45.y, acc5);
        acc6 = fma2(h, m67.x, acc6); acc7 = fma2(h, m67.y, acc7);
    }

    const float4* ea4 = (const float4*)ea;
    float4 eA0 = ea4[4 * p + 0], eA1 = ea4[4 * p + 1];
    float4 eB0 = ea4[4 * p + 2], eB1 = ea4[4 * p + 3];
    float lo, hi;
    float4 oA0, oA1, oB0, oB1;
    unpack2(acc0, lo, hi); oA0.x = eA0.x + lo; oB0.x = eB0.x + hi;
    unpack2(acc1, lo, hi); oA0.y = eA0.y + lo; oB0.y = eB0.y + hi;
    unpack2(acc2, lo, hi); oA0.z = eA0.z + lo; oB0.z = eB0.z + hi;
    unpack2(acc3, lo, hi); oA0.w = eA0.w + lo; oB0.w = eB0.w + hi;
    unpack2(acc4, lo, hi); oA1.x = eA1.x + lo; oB1.x = eB1.x + hi;
    unpack2(acc5, lo, hi); oA1.y = eA1.y + lo; oB1.y = eB1.y + hi;
    unpack2(acc6, lo, hi); oA1.z = eA1.z + lo; oB1.z = eB1.z + hi;
    unpack2(acc7, lo, hi); oA1.w = eA1.w + lo; oB1.w = eB1.w + hi;

    float4* out4 = (float4*)out;
    out4[4 * p + 0] = oA0;
    out4[4 * p + 1] = oA1;
    out4[4 * p + 2] = oB0;
    out4[4 * p + 3] = oB1;
}

// -------- launch --------
extern "C" void kernel_launch(void* const* d_in, const int* in_sizes, int n_in,
                              void* d_out, int out_size) {
    (void)in_sizes; (void)n_in; (void)out_size;
    const float* edge_attr = (const float*)d_in[0];
    const float* nf        = (const float*)d_in[1];
    const int*   eidx      = (const int*)d_in[2];
    // d_in[3..8] = edge-encoder weights: provably dead code in the reference
    const float* W1    = (const float*)d_in[9];
    const float* b1    = (const float*)d_in[10];
    const float* gamma = (const float*)d_in[11];
    const float* beta  = (const float*)d_in[12];
    const float* W2    = (const float*)d_in[13];
    const float* b2    = (const float*)d_in[14];
    const float* Wv    = (const float*)d_in[15];
    const float* bv    = (const float*)d_in[16];
    const float* Wo    = (const float*)d_in[17];
    const float* bo    = (const float*)d_in[18];
    const float* Wp    = (const float*)d_in[19];
    const float* bp    = (const float*)d_in[20];
    float* out = (float*)d_out;

    kA<<<8, 256>>>(Wo, Wp, W1, b1);      // P1, w1dup, b1dup, zero stats
    k1<<<NBLK1, 256>>>(eidx, nf);        // gather + cache nc + relu stats
    kB<<<8, 256>>>(Wv);                  // P2
    kV<<<1, 256>>>(gamma, beta, W2, b2, Wv, bv, Wo, bo, Wp, bp);  // a, c, dh
    kC<<<8, 256>>>(W2);                  // M (duplicated, 0.5-folded)
    k3<<<NBLK1, 256>>>(edge_attr, out);  // main contraction + epilogue
}